// round 2
// baseline (speedup 1.0000x reference)
#include <cuda_runtime.h>

// GRUAdder: B ~ 1M, T=4, I=2, H=16.
// Outputs (concatenated, float32): hidden_table [B,4,16], sum_logits [B,4],
// carry_logit [B,1], output_logits [B,5]  => 74 floats per batch row.

#define TT 4
#define II 2
#define HH 16
#define G  48   // 3*H

typedef unsigned long long ull;

__device__ __forceinline__ ull ffma2(ull a, ull b, ull c) {
    ull d;
    asm("fma.rn.f32x2 %0, %1, %2, %3;" : "=l"(d) : "l"(a), "l"(b), "l"(c));
    return d;
}
__device__ __forceinline__ ull pk2(float lo, float hi) {
    ull r;
    asm("mov.b64 %0, {%1, %2};" : "=l"(r) : "f"(lo), "f"(hi));
    return r;
}
__device__ __forceinline__ void upk2(float& lo, float& hi, ull v) {
    asm("mov.b64 {%0, %1}, %2;" : "=f"(lo), "=f"(hi) : "l"(v));
}

__device__ __forceinline__ float fsig(float x) {
    // sigmoid(x) = 1 / (1 + exp(-x)), exp via ex2.approx (rel err ~2^-22)
    float e, r;
    asm("ex2.approx.f32 %0, %1;" : "=f"(e) : "f"(-1.4426950408889634f * x));
    asm("rcp.approx.f32 %0, %1;" : "=f"(r) : "f"(1.0f + e));
    return r;
}

__device__ __forceinline__ float ftanh_fast(float x) {
    // tanh(x) = 2/(1+exp(-2x)) - 1
    float e, r;
    asm("ex2.approx.f32 %0, %1;" : "=f"(e) : "f"(-2.8853900817779268f * x));
    asm("rcp.approx.f32 %0, %1;" : "=f"(r) : "f"(1.0f + e));
    return 2.0f * r - 1.0f;
}

__global__ void __launch_bounds__(256, 2) gru_adder_kernel(
    const float* __restrict__ x,        // [B, 4, 2]
    const float* __restrict__ w_ih,     // [48, 2]
    const float* __restrict__ w_hh,     // [48, 16]
    const float* __restrict__ b_ih,     // [48]
    const float* __restrict__ b_hh,     // [48]
    const float* __restrict__ w_sum,    // [1, 16]
    const float* __restrict__ b_sum,    // [1]
    const float* __restrict__ w_carry,  // [1, 16]
    const float* __restrict__ b_carry,  // [1]
    float* __restrict__ hid,            // [B, 4, 16] or null
    float* __restrict__ sumo,           // [B, 4] or null
    float* __restrict__ carryo,         // [B] or null
    float* __restrict__ olog,           // [B, 5] or null
    int B)
{
    // Transposed W_hh: row k holds w_hh[j][k] for j=0..47 (192B rows, 16B aligned)
    __shared__ __align__(16) float s_whhT[HH][G];
    __shared__ __align__(16) float s_wih0[G], s_wih1[G];
    __shared__ __align__(16) float s_brz[32];   // b_ih + b_hh, gates 0..31
    __shared__ __align__(16) float s_bin[HH];   // b_ih, n gate
    __shared__ __align__(16) float s_bhn[HH];   // b_hh, n gate
    __shared__ __align__(16) float s_wsum[HH], s_wcar[HH];
    __shared__ float s_bs, s_bc;

    for (int idx = threadIdx.x; idx < G * HH; idx += blockDim.x) {
        int j = idx / HH, k = idx % HH;
        s_whhT[k][j] = w_hh[idx];
    }
    for (int j = threadIdx.x; j < G; j += blockDim.x) {
        s_wih0[j] = w_ih[j * II + 0];
        s_wih1[j] = w_ih[j * II + 1];
        if (j < 32) {
            s_brz[j] = b_ih[j] + b_hh[j];
        } else {
            s_bin[j - 32] = b_ih[j];
            s_bhn[j - 32] = b_hh[j];
        }
        if (j < HH) { s_wsum[j] = w_sum[j]; s_wcar[j] = w_carry[j]; }
        if (j == 0) { s_bs = b_sum[0]; s_bc = b_carry[0]; }
    }
    __syncthreads();

    int b = blockIdx.x * blockDim.x + threadIdx.x;
    if (b >= B) return;

    float h[HH];
    #pragma unroll
    for (int j = 0; j < HH; j++) h[j] = 0.0f;

    #pragma unroll 1
    for (int t = 0; t < TT; t++) {
        const float2 xv = *reinterpret_cast<const float2*>(x + (size_t)b * (TT * II) + t * II);
        const ull x0d = pk2(xv.x, xv.x);
        const ull x1d = pk2(xv.y, xv.y);

        // Pair p covers gates (2p, 2p+1):
        //   acc[0..7]  : r pre-activations (gates 0..15), incl. biases
        //   acc[8..15] : z pre-activations (gates 16..31), incl. biases
        //   acc[16..23]: h_n part only (gates 32..47), b_hh included
        //   gin[0..7]  : i_n part (gates 32..47), b_ih included
        ull acc[24], gin[8];

        #pragma unroll
        for (int g = 0; g < 8; g++) {   // r/z gates: 4g..4g+3
            ulonglong2 w0 = *reinterpret_cast<const ulonglong2*>(&s_wih0[4 * g]);
            ulonglong2 w1 = *reinterpret_cast<const ulonglong2*>(&s_wih1[4 * g]);
            ulonglong2 bb = *reinterpret_cast<const ulonglong2*>(&s_brz[4 * g]);
            acc[2 * g + 0] = ffma2(w1.x, x1d, ffma2(w0.x, x0d, bb.x));
            acc[2 * g + 1] = ffma2(w1.y, x1d, ffma2(w0.y, x0d, bb.y));
        }
        #pragma unroll
        for (int g = 0; g < 4; g++) {   // n gates: 32+4g..32+4g+3
            ulonglong2 w0 = *reinterpret_cast<const ulonglong2*>(&s_wih0[32 + 4 * g]);
            ulonglong2 w1 = *reinterpret_cast<const ulonglong2*>(&s_wih1[32 + 4 * g]);
            ulonglong2 bi = *reinterpret_cast<const ulonglong2*>(&s_bin[4 * g]);
            ulonglong2 bh = *reinterpret_cast<const ulonglong2*>(&s_bhn[4 * g]);
            gin[2 * g + 0] = ffma2(w1.x, x1d, ffma2(w0.x, x0d, bi.x));
            gin[2 * g + 1] = ffma2(w1.y, x1d, ffma2(w0.y, x0d, bi.y));
            acc[16 + 2 * g + 0] = bh.x;
            acc[16 + 2 * g + 1] = bh.y;
        }

        // Recurrent matvec: acc[p] += (w_hh[2p][k], w_hh[2p+1][k]) * (h_k, h_k)
        #pragma unroll
        for (int k = 0; k < HH; k++) {
            const ull hd = pk2(h[k], h[k]);
            #pragma unroll
            for (int g = 0; g < 12; g++) {
                ulonglong2 w = *reinterpret_cast<const ulonglong2*>(&s_whhT[k][4 * g]);
                acc[2 * g + 0] = ffma2(w.x, hd, acc[2 * g + 0]);
                acc[2 * g + 1] = ffma2(w.y, hd, acc[2 * g + 1]);
            }
        }

        // Activations + state update + sum head
        ull s2 = pk2(s_bs, 0.0f);
        #pragma unroll
        for (int p = 0; p < 8; p++) {
            float ar0, ar1, az0, az1, an0, an1, gi0, gi1;
            upk2(ar0, ar1, acc[p]);
            upk2(az0, az1, acc[8 + p]);
            upk2(an0, an1, acc[16 + p]);
            upk2(gi0, gi1, gin[p]);
            float r0 = fsig(ar0), r1 = fsig(ar1);
            float z0 = fsig(az0), z1 = fsig(az1);
            float n0 = ftanh_fast(gi0 + r0 * an0);
            float n1 = ftanh_fast(gi1 + r1 * an1);
            float hn0 = n0 + z0 * (h[2 * p + 0] - n0);  // (1-z)*n + z*h
            float hn1 = n1 + z1 * (h[2 * p + 1] - n1);
            h[2 * p + 0] = hn0;
            h[2 * p + 1] = hn1;
            ull ws = *reinterpret_cast<const ull*>(&s_wsum[2 * p]);
            s2 = ffma2(pk2(hn0, hn1), ws, s2);
        }
        float slo, shi;
        upk2(slo, shi, s2);
        const float s = slo + shi;

        if (hid) {
            float4* hp = reinterpret_cast<float4*>(hid + (size_t)b * (TT * HH) + t * HH);
            hp[0] = make_float4(h[0],  h[1],  h[2],  h[3]);
            hp[1] = make_float4(h[4],  h[5],  h[6],  h[7]);
            hp[2] = make_float4(h[8],  h[9],  h[10], h[11]);
            hp[3] = make_float4(h[12], h[13], h[14], h[15]);
        }
        if (sumo) sumo[(size_t)b * TT + t] = s;
        if (olog) olog[(size_t)b * (TT + 1) + t] = s;
    }

    float c = s_bc;
    #pragma unroll
    for (int j = 0; j < HH; j++) c += h[j] * s_wcar[j];
    if (carryo) carryo[b] = c;
    if (olog)   olog[(size_t)b * (TT + 1) + TT] = c;
}

extern "C" void kernel_launch(void* const* d_in, const int* in_sizes, int n_in,
                              void* d_out, int out_size) {
    const float* x       = (const float*)d_in[0];
    const float* w_ih    = (const float*)d_in[1];
    const float* w_hh    = (const float*)d_in[2];
    const float* b_ih    = (const float*)d_in[3];
    const float* b_hh    = (const float*)d_in[4];
    const float* w_sum   = (const float*)d_in[5];
    const float* b_sum   = (const float*)d_in[6];
    const float* w_carry = (const float*)d_in[7];
    const float* b_carry = (const float*)d_in[8];

    long long B = (long long)in_sizes[0] / (TT * II);
    float* out = (float*)d_out;
    long long os = (long long)out_size;

    // Output layout: concatenation of flattened (hidden_table, sum_logits,
    // carry_logit, output_logits) = 74 floats per row; fall back otherwise.
    float *hid = nullptr, *sum = nullptr, *car = nullptr, *olog = nullptr;
    if (os >= B * 74) {
        hid = out; sum = out + B * 64; car = out + B * 68; olog = out + B * 69;
    } else if (os >= B * 64) {
        hid = out;
    } else if (os >= B * 5) {
        olog = out;
    } else if (os >= B * 4) {
        sum = out;
    } else {
        car = out;
    }

    const int threads = 256;
    int grid = (int)((B + threads - 1) / threads);
    gru_adder_kernel<<<grid, threads>>>(x, w_ih, w_hh, b_ih, b_hh,
                                        w_sum, b_sum, w_carry, b_carry,
                                        hid, sum, car, olog, (int)B);
}

// round 4
// speedup vs baseline: 7.9399x; 7.9399x over previous
#include <cuda_runtime.h>

// GRUAdder: B = 1048576, T=4, I=2, H=16.
// Two threads per batch row: lane `half` owns h[8*half .. 8*half+7] and its
// 24 gate accumulators. Full h exchanged via warp shuffles each k-step.

#define TT 4
#define II 2
#define HH 16
#define G  48   // 3*H

typedef unsigned long long ull;

__device__ __forceinline__ ull ffma2(ull a, ull b, ull c) {
    ull d;
    asm("fma.rn.f32x2 %0, %1, %2, %3;" : "=l"(d) : "l"(a), "l"(b), "l"(c));
    return d;
}
__device__ __forceinline__ ull pk2(float lo, float hi) {
    ull r;
    asm("mov.b64 %0, {%1, %2};" : "=l"(r) : "f"(lo), "f"(hi));
    return r;
}
__device__ __forceinline__ void upk2(float& lo, float& hi, ull v) {
    asm("mov.b64 {%0, %1}, %2;" : "=f"(lo), "=f"(hi) : "l"(v));
}

__device__ __forceinline__ float fsig(float x) {
    // sigmoid(x) = 1 / (1 + exp(-x)); exp via ex2.approx (rel err ~2^-22)
    float e, r;
    asm("ex2.approx.f32 %0, %1;" : "=f"(e) : "f"(-1.4426950408889634f * x));
    asm("rcp.approx.f32 %0, %1;" : "=f"(r) : "f"(1.0f + e));
    return r;
}
__device__ __forceinline__ float ftanh_fast(float x) {
    // tanh(x) = 2/(1+exp(-2x)) - 1
    float e, r;
    asm("ex2.approx.f32 %0, %1;" : "=f"(e) : "f"(-2.8853900817779268f * x));
    asm("rcp.approx.f32 %0, %1;" : "=f"(r) : "f"(1.0f + e));
    return 2.0f * r - 1.0f;
}

__global__ void __launch_bounds__(256) gru_adder_kernel(
    const float* __restrict__ x,        // [B, 4, 2]
    const float* __restrict__ w_ih,     // [48, 2]
    const float* __restrict__ w_hh,     // [48, 16]
    const float* __restrict__ b_ih,     // [48]
    const float* __restrict__ b_hh,     // [48]
    const float* __restrict__ w_sum,    // [1, 16]
    const float* __restrict__ b_sum,    // [1]
    const float* __restrict__ w_carry,  // [1, 16]
    const float* __restrict__ b_carry,  // [1]
    float* __restrict__ hid,            // [B, 4, 16] or null
    float* __restrict__ sumo,           // [B, 4] or null
    float* __restrict__ carryo,         // [B] or null
    float* __restrict__ olog,           // [B, 5] or null
    int B)
{
    // Transposed W_hh: s_whhT[k][j] = w_hh[j][k]; row = 192B, 16B-aligned.
    __shared__ __align__(16) float s_whhT[HH][G];
    __shared__ __align__(16) float s_wih0[G], s_wih1[G];
    __shared__ __align__(16) float s_brz[32];   // b_ih + b_hh for gates 0..31
    __shared__ __align__(16) float s_bin[HH];   // b_ih for n gate
    __shared__ __align__(16) float s_bhn[HH];   // b_hh for n gate
    __shared__ __align__(16) float s_wsum[HH], s_wcar[HH];
    __shared__ float s_bs, s_bc;

    for (int idx = threadIdx.x; idx < G * HH; idx += blockDim.x) {
        int j = idx / HH, k = idx % HH;
        s_whhT[k][j] = w_hh[idx];
    }
    for (int j = threadIdx.x; j < G; j += blockDim.x) {
        s_wih0[j] = w_ih[j * II + 0];
        s_wih1[j] = w_ih[j * II + 1];
        if (j < 32) {
            s_brz[j] = b_ih[j] + b_hh[j];
        } else {
            s_bin[j - 32] = b_ih[j];
            s_bhn[j - 32] = b_hh[j];
        }
        if (j < HH) { s_wsum[j] = w_sum[j]; s_wcar[j] = w_carry[j]; }
        if (j == 0) { s_bs = b_sum[0]; s_bc = b_carry[0]; }
    }
    __syncthreads();

    const int tid  = blockIdx.x * blockDim.x + threadIdx.x;
    const int row  = tid >> 1;          // batch row
    const int half = tid & 1;           // which 8 h-elements this lane owns
    if (row >= B) return;               // B is a multiple of 128 -> warp-uniform

    const int lane  = threadIdx.x & 31;
    const int jbase = half * 8;         // global j offset of owned h slice

    // Lane-local weight row pointers (within shared)
    const float* wih0R = &s_wih0[jbase];
    const float* wih0Z = &s_wih0[16 + jbase];
    const float* wih0N = &s_wih0[32 + jbase];
    const float* wih1R = &s_wih1[jbase];
    const float* wih1Z = &s_wih1[16 + jbase];
    const float* wih1N = &s_wih1[32 + jbase];

    float h[8];
    #pragma unroll
    for (int i = 0; i < 8; i++) h[i] = 0.0f;

    const float* xr = x + (size_t)row * (TT * II);

    #pragma unroll 1
    for (int t = 0; t < TT; t++) {
        const float2 xv = *reinterpret_cast<const float2*>(xr + t * II);
        const ull x0d = pk2(xv.x, xv.x);
        const ull x1d = pk2(xv.y, xv.y);

        // accR/accZ: full r/z pre-activations (biases included)
        // accN: h_n recurrent part (b_hh included); ginN: i_n part (b_ih included)
        ull accR[4], accZ[4], accN[4], ginN[4];

        #pragma unroll
        for (int g = 0; g < 2; g++) {
            ulonglong2 w0r = reinterpret_cast<const ulonglong2*>(wih0R)[g];
            ulonglong2 w1r = reinterpret_cast<const ulonglong2*>(wih1R)[g];
            ulonglong2 br  = reinterpret_cast<const ulonglong2*>(&s_brz[jbase])[g];
            accR[2*g+0] = ffma2(w1r.x, x1d, ffma2(w0r.x, x0d, br.x));
            accR[2*g+1] = ffma2(w1r.y, x1d, ffma2(w0r.y, x0d, br.y));

            ulonglong2 w0z = reinterpret_cast<const ulonglong2*>(wih0Z)[g];
            ulonglong2 w1z = reinterpret_cast<const ulonglong2*>(wih1Z)[g];
            ulonglong2 bz  = reinterpret_cast<const ulonglong2*>(&s_brz[16 + jbase])[g];
            accZ[2*g+0] = ffma2(w1z.x, x1d, ffma2(w0z.x, x0d, bz.x));
            accZ[2*g+1] = ffma2(w1z.y, x1d, ffma2(w0z.y, x0d, bz.y));

            ulonglong2 w0n = reinterpret_cast<const ulonglong2*>(wih0N)[g];
            ulonglong2 w1n = reinterpret_cast<const ulonglong2*>(wih1N)[g];
            ulonglong2 bi  = reinterpret_cast<const ulonglong2*>(&s_bin[jbase])[g];
            ulonglong2 bh  = reinterpret_cast<const ulonglong2*>(&s_bhn[jbase])[g];
            ginN[2*g+0] = ffma2(w1n.x, x1d, ffma2(w0n.x, x0d, bi.x));
            ginN[2*g+1] = ffma2(w1n.y, x1d, ffma2(w0n.y, x0d, bi.y));
            accN[2*g+0] = bh.x;
            accN[2*g+1] = bh.y;
        }

        // Recurrent matvec: acc_j += w_hh[j][k] * h_global[k]
        #pragma unroll
        for (int k = 0; k < HH; k++) {
            const int src = (lane & ~1) | (k >> 3);
            const float hk = __shfl_sync(0xffffffffu, h[k & 7], src);
            const ull hd = pk2(hk, hk);

            const float* wr = &s_whhT[k][jbase];
            ulonglong2 wRa = *reinterpret_cast<const ulonglong2*>(wr);
            ulonglong2 wRb = *reinterpret_cast<const ulonglong2*>(wr + 4);
            ulonglong2 wZa = *reinterpret_cast<const ulonglong2*>(wr + 16);
            ulonglong2 wZb = *reinterpret_cast<const ulonglong2*>(wr + 20);
            ulonglong2 wNa = *reinterpret_cast<const ulonglong2*>(wr + 32);
            ulonglong2 wNb = *reinterpret_cast<const ulonglong2*>(wr + 36);

            accR[0] = ffma2(wRa.x, hd, accR[0]);
            accR[1] = ffma2(wRa.y, hd, accR[1]);
            accR[2] = ffma2(wRb.x, hd, accR[2]);
            accR[3] = ffma2(wRb.y, hd, accR[3]);
            accZ[0] = ffma2(wZa.x, hd, accZ[0]);
            accZ[1] = ffma2(wZa.y, hd, accZ[1]);
            accZ[2] = ffma2(wZb.x, hd, accZ[2]);
            accZ[3] = ffma2(wZb.y, hd, accZ[3]);
            accN[0] = ffma2(wNa.x, hd, accN[0]);
            accN[1] = ffma2(wNa.y, hd, accN[1]);
            accN[2] = ffma2(wNb.x, hd, accN[2]);
            accN[3] = ffma2(wNb.y, hd, accN[3]);
        }

        // Activations + state update + sum-head partial
        float sp = 0.0f;
        #pragma unroll
        for (int p = 0; p < 4; p++) {
            float ar0, ar1, az0, az1, an0, an1, gi0, gi1;
            upk2(ar0, ar1, accR[p]);
            upk2(az0, az1, accZ[p]);
            upk2(an0, an1, accN[p]);
            upk2(gi0, gi1, ginN[p]);
            float r0 = fsig(ar0), r1 = fsig(ar1);
            float z0 = fsig(az0), z1 = fsig(az1);
            float n0 = ftanh_fast(gi0 + r0 * an0);
            float n1 = ftanh_fast(gi1 + r1 * an1);
            float h0 = n0 + z0 * (h[2*p+0] - n0);   // (1-z)*n + z*h
            float h1 = n1 + z1 * (h[2*p+1] - n1);
            h[2*p+0] = h0;
            h[2*p+1] = h1;
            sp += h0 * s_wsum[jbase + 2*p] + h1 * s_wsum[jbase + 2*p + 1];
        }
        // FIX (round 3 bug): include the sum-head bias s_bs
        const float s = s_bs + sp + __shfl_xor_sync(0xffffffffu, sp, 1);

        if (hid) {
            float4* hp = reinterpret_cast<float4*>(
                hid + (size_t)row * (TT * HH) + t * HH + jbase);
            hp[0] = make_float4(h[0], h[1], h[2], h[3]);
            hp[1] = make_float4(h[4], h[5], h[6], h[7]);
        }
        if (half == 0) {
            if (sumo) sumo[(size_t)row * TT + t] = s;
        } else {
            if (olog) olog[(size_t)row * (TT + 1) + t] = s;
        }
    }

    float cp = 0.0f;
    #pragma unroll
    for (int i = 0; i < 8; i++) cp += h[i] * s_wcar[jbase + i];
    // FIX (round 3 bug): include the carry-head bias s_bc
    const float c = s_bc + cp + __shfl_xor_sync(0xffffffffu, cp, 1);
    if (half == 0) {
        if (carryo) carryo[row] = c;
    } else {
        if (olog) olog[(size_t)row * (TT + 1) + TT] = c;
    }
}

extern "C" void kernel_launch(void* const* d_in, const int* in_sizes, int n_in,
                              void* d_out, int out_size) {
    const float* x       = (const float*)d_in[0];
    const float* w_ih    = (const float*)d_in[1];
    const float* w_hh    = (const float*)d_in[2];
    const float* b_ih    = (const float*)d_in[3];
    const float* b_hh    = (const float*)d_in[4];
    const float* w_sum   = (const float*)d_in[5];
    const float* b_sum   = (const float*)d_in[6];
    const float* w_carry = (const float*)d_in[7];
    const float* b_carry = (const float*)d_in[8];

    long long B = (long long)in_sizes[0] / (TT * II);
    float* out = (float*)d_out;
    long long os = (long long)out_size;

    // Output layout: concatenation of flattened (hidden_table, sum_logits,
    // carry_logit, output_logits) = 74 floats per row; fall back otherwise.
    float *hid = nullptr, *sum = nullptr, *car = nullptr, *olog = nullptr;
    if (os >= B * 74) {
        hid = out; sum = out + B * 64; car = out + B * 68; olog = out + B * 69;
    } else if (os >= B * 64) {
        hid = out;
    } else if (os >= B * 5) {
        olog = out;
    } else if (os >= B * 4) {
        sum = out;
    } else {
        car = out;
    }

    const int threads = 256;
    long long total = B * 2;
    int grid = (int)((total + threads - 1) / threads);
    gru_adder_kernel<<<grid, threads>>>(x, w_ih, w_hh, b_ih, b_hh,
                                        w_sum, b_sum, w_carry, b_carry,
                                        hid, sum, car, olog, (int)B);
}

// round 5
// speedup vs baseline: 11.3598x; 1.4307x over previous
#include <cuda_runtime.h>

// GRUAdder: B = 1048576, T=4, I=2, H=16.
// 2 lanes per batch row (half-split of h) x 2 rows per thread:
// each weight LDS.128 feeds 4 ffma2 (2 gates x 2 rows).

#define TT 4
#define II 2
#define HH 16
#define G  48   // 3*H

typedef unsigned long long ull;

__device__ __forceinline__ ull ffma2(ull a, ull b, ull c) {
    ull d;
    asm("fma.rn.f32x2 %0, %1, %2, %3;" : "=l"(d) : "l"(a), "l"(b), "l"(c));
    return d;
}
__device__ __forceinline__ ull pk2(float lo, float hi) {
    ull r;
    asm("mov.b64 %0, {%1, %2};" : "=l"(r) : "f"(lo), "f"(hi));
    return r;
}
__device__ __forceinline__ void upk2(float& lo, float& hi, ull v) {
    asm("mov.b64 {%0, %1}, %2;" : "=f"(lo), "=f"(hi) : "l"(v));
}

__device__ __forceinline__ float fsig(float x) {
    float e, r;
    asm("ex2.approx.f32 %0, %1;" : "=f"(e) : "f"(-1.4426950408889634f * x));
    asm("rcp.approx.f32 %0, %1;" : "=f"(r) : "f"(1.0f + e));
    return r;
}
__device__ __forceinline__ float ftanh_fast(float x) {
    float e, r;
    asm("ex2.approx.f32 %0, %1;" : "=f"(e) : "f"(-2.8853900817779268f * x));
    asm("rcp.approx.f32 %0, %1;" : "=f"(r) : "f"(1.0f + e));
    return 2.0f * r - 1.0f;
}

__global__ void __launch_bounds__(256) gru_adder_kernel(
    const float* __restrict__ x,        // [B, 4, 2]
    const float* __restrict__ w_ih,     // [48, 2]
    const float* __restrict__ w_hh,     // [48, 16]
    const float* __restrict__ b_ih,     // [48]
    const float* __restrict__ b_hh,     // [48]
    const float* __restrict__ w_sum,    // [1, 16]
    const float* __restrict__ b_sum,    // [1]
    const float* __restrict__ w_carry,  // [1, 16]
    const float* __restrict__ b_carry,  // [1]
    float* __restrict__ hid,            // [B, 4, 16] or null
    float* __restrict__ sumo,           // [B, 4] or null
    float* __restrict__ carryo,         // [B] or null
    float* __restrict__ olog,           // [B, 5] or null
    int B)
{
    // Transposed W_hh: s_whhT[k][j] = w_hh[j][k]; row = 192B, 16B-aligned.
    __shared__ __align__(16) float s_whhT[HH][G];
    __shared__ __align__(16) float s_wih0[G], s_wih1[G];
    __shared__ __align__(16) float s_brz[32];   // b_ih + b_hh, gates 0..31
    __shared__ __align__(16) float s_bin[HH];   // b_ih, n gate
    __shared__ __align__(16) float s_bhn[HH];   // b_hh, n gate
    __shared__ __align__(16) float s_wsum[HH], s_wcar[HH];
    __shared__ float s_bs, s_bc;

    for (int idx = threadIdx.x; idx < G * HH; idx += blockDim.x) {
        int j = idx / HH, k = idx % HH;
        s_whhT[k][j] = w_hh[idx];
    }
    for (int j = threadIdx.x; j < G; j += blockDim.x) {
        s_wih0[j] = w_ih[j * II + 0];
        s_wih1[j] = w_ih[j * II + 1];
        if (j < 32) {
            s_brz[j] = b_ih[j] + b_hh[j];
        } else {
            s_bin[j - 32] = b_ih[j];
            s_bhn[j - 32] = b_hh[j];
        }
        if (j < HH) { s_wsum[j] = w_sum[j]; s_wcar[j] = w_carry[j]; }
        if (j == 0) { s_bs = b_sum[0]; s_bc = b_carry[0]; }
    }
    __syncthreads();

    const int tid  = blockIdx.x * blockDim.x + threadIdx.x;
    const int pr   = tid >> 1;          // row-pair index -> rows 2pr, 2pr+1
    const int half = tid & 1;           // which 8 h-elements this lane owns
    const long long rowA = (long long)pr * 2;
    if (rowA >= B) return;              // warp-uniform (B multiple of 256)

    const int lane  = threadIdx.x & 31;
    const int jbase = half * 8;

    float hA[8], hB[8];
    #pragma unroll
    for (int i = 0; i < 8; i++) { hA[i] = 0.0f; hB[i] = 0.0f; }

    const float* xr = x + rowA * (TT * II);   // 16 floats: rowA then rowA+1

    #pragma unroll 1
    for (int t = 0; t < TT; t++) {
        const float2 xvA = *reinterpret_cast<const float2*>(xr + t * II);
        const float2 xvB = *reinterpret_cast<const float2*>(xr + TT * II + t * II);
        const ull xA0 = pk2(xvA.x, xvA.x), xA1 = pk2(xvA.y, xvA.y);
        const ull xB0 = pk2(xvB.x, xvB.x), xB1 = pk2(xvB.y, xvB.y);

        ull aR[2][4], aZ[2][4], aN[2][4], gN[2][4];

        #pragma unroll
        for (int g = 0; g < 2; g++) {
            ulonglong2 w0r = *reinterpret_cast<const ulonglong2*>(&s_wih0[jbase + 4*g]);
            ulonglong2 w1r = *reinterpret_cast<const ulonglong2*>(&s_wih1[jbase + 4*g]);
            ulonglong2 br  = *reinterpret_cast<const ulonglong2*>(&s_brz[jbase + 4*g]);
            aR[0][2*g+0] = ffma2(w1r.x, xA1, ffma2(w0r.x, xA0, br.x));
            aR[0][2*g+1] = ffma2(w1r.y, xA1, ffma2(w0r.y, xA0, br.y));
            aR[1][2*g+0] = ffma2(w1r.x, xB1, ffma2(w0r.x, xB0, br.x));
            aR[1][2*g+1] = ffma2(w1r.y, xB1, ffma2(w0r.y, xB0, br.y));

            ulonglong2 w0z = *reinterpret_cast<const ulonglong2*>(&s_wih0[16 + jbase + 4*g]);
            ulonglong2 w1z = *reinterpret_cast<const ulonglong2*>(&s_wih1[16 + jbase + 4*g]);
            ulonglong2 bz  = *reinterpret_cast<const ulonglong2*>(&s_brz[16 + jbase + 4*g]);
            aZ[0][2*g+0] = ffma2(w1z.x, xA1, ffma2(w0z.x, xA0, bz.x));
            aZ[0][2*g+1] = ffma2(w1z.y, xA1, ffma2(w0z.y, xA0, bz.y));
            aZ[1][2*g+0] = ffma2(w1z.x, xB1, ffma2(w0z.x, xB0, bz.x));
            aZ[1][2*g+1] = ffma2(w1z.y, xB1, ffma2(w0z.y, xB0, bz.y));

            ulonglong2 w0n = *reinterpret_cast<const ulonglong2*>(&s_wih0[32 + jbase + 4*g]);
            ulonglong2 w1n = *reinterpret_cast<const ulonglong2*>(&s_wih1[32 + jbase + 4*g]);
            ulonglong2 bi  = *reinterpret_cast<const ulonglong2*>(&s_bin[jbase + 4*g]);
            ulonglong2 bh  = *reinterpret_cast<const ulonglong2*>(&s_bhn[jbase + 4*g]);
            gN[0][2*g+0] = ffma2(w1n.x, xA1, ffma2(w0n.x, xA0, bi.x));
            gN[0][2*g+1] = ffma2(w1n.y, xA1, ffma2(w0n.y, xA0, bi.y));
            gN[1][2*g+0] = ffma2(w1n.x, xB1, ffma2(w0n.x, xB0, bi.x));
            gN[1][2*g+1] = ffma2(w1n.y, xB1, ffma2(w0n.y, xB0, bi.y));
            aN[0][2*g+0] = bh.x;  aN[0][2*g+1] = bh.y;
            aN[1][2*g+0] = bh.x;  aN[1][2*g+1] = bh.y;
        }

        // Recurrent matvec: each weight load feeds both rows.
        #pragma unroll
        for (int k = 0; k < HH; k++) {
            const int src = (lane & ~1) | (k >> 3);
            const float hkA = __shfl_sync(0xffffffffu, hA[k & 7], src);
            const float hkB = __shfl_sync(0xffffffffu, hB[k & 7], src);
            const ull hdA = pk2(hkA, hkA);
            const ull hdB = pk2(hkB, hkB);

            const float* wr = &s_whhT[k][jbase];
            ulonglong2 wRa = *reinterpret_cast<const ulonglong2*>(wr);
            ulonglong2 wRb = *reinterpret_cast<const ulonglong2*>(wr + 4);
            ulonglong2 wZa = *reinterpret_cast<const ulonglong2*>(wr + 16);
            ulonglong2 wZb = *reinterpret_cast<const ulonglong2*>(wr + 20);
            ulonglong2 wNa = *reinterpret_cast<const ulonglong2*>(wr + 32);
            ulonglong2 wNb = *reinterpret_cast<const ulonglong2*>(wr + 36);

            aR[0][0] = ffma2(wRa.x, hdA, aR[0][0]);
            aR[0][1] = ffma2(wRa.y, hdA, aR[0][1]);
            aR[0][2] = ffma2(wRb.x, hdA, aR[0][2]);
            aR[0][3] = ffma2(wRb.y, hdA, aR[0][3]);
            aR[1][0] = ffma2(wRa.x, hdB, aR[1][0]);
            aR[1][1] = ffma2(wRa.y, hdB, aR[1][1]);
            aR[1][2] = ffma2(wRb.x, hdB, aR[1][2]);
            aR[1][3] = ffma2(wRb.y, hdB, aR[1][3]);

            aZ[0][0] = ffma2(wZa.x, hdA, aZ[0][0]);
            aZ[0][1] = ffma2(wZa.y, hdA, aZ[0][1]);
            aZ[0][2] = ffma2(wZb.x, hdA, aZ[0][2]);
            aZ[0][3] = ffma2(wZb.y, hdA, aZ[0][3]);
            aZ[1][0] = ffma2(wZa.x, hdB, aZ[1][0]);
            aZ[1][1] = ffma2(wZa.y, hdB, aZ[1][1]);
            aZ[1][2] = ffma2(wZb.x, hdB, aZ[1][2]);
            aZ[1][3] = ffma2(wZb.y, hdB, aZ[1][3]);

            aN[0][0] = ffma2(wNa.x, hdA, aN[0][0]);
            aN[0][1] = ffma2(wNa.y, hdA, aN[0][1]);
            aN[0][2] = ffma2(wNb.x, hdA, aN[0][2]);
            aN[0][3] = ffma2(wNb.y, hdA, aN[0][3]);
            aN[1][0] = ffma2(wNa.x, hdB, aN[1][0]);
            aN[1][1] = ffma2(wNa.y, hdB, aN[1][1]);
            aN[1][2] = ffma2(wNb.x, hdB, aN[1][2]);
            aN[1][3] = ffma2(wNb.y, hdB, aN[1][3]);
        }

        // Activations + state update + sum-head partials (both rows)
        float spA = 0.0f, spB = 0.0f;
        #pragma unroll
        for (int p = 0; p < 4; p++) {
            const float ws0 = s_wsum[jbase + 2*p];
            const float ws1 = s_wsum[jbase + 2*p + 1];
            {
                float ar0, ar1, az0, az1, an0, an1, gi0, gi1;
                upk2(ar0, ar1, aR[0][p]);
                upk2(az0, az1, aZ[0][p]);
                upk2(an0, an1, aN[0][p]);
                upk2(gi0, gi1, gN[0][p]);
                float r0 = fsig(ar0), r1 = fsig(ar1);
                float z0 = fsig(az0), z1 = fsig(az1);
                float n0 = ftanh_fast(gi0 + r0 * an0);
                float n1 = ftanh_fast(gi1 + r1 * an1);
                float h0 = n0 + z0 * (hA[2*p+0] - n0);
                float h1 = n1 + z1 * (hA[2*p+1] - n1);
                hA[2*p+0] = h0; hA[2*p+1] = h1;
                spA += h0 * ws0 + h1 * ws1;
            }
            {
                float ar0, ar1, az0, az1, an0, an1, gi0, gi1;
                upk2(ar0, ar1, aR[1][p]);
                upk2(az0, az1, aZ[1][p]);
                upk2(an0, an1, aN[1][p]);
                upk2(gi0, gi1, gN[1][p]);
                float r0 = fsig(ar0), r1 = fsig(ar1);
                float z0 = fsig(az0), z1 = fsig(az1);
                float n0 = ftanh_fast(gi0 + r0 * an0);
                float n1 = ftanh_fast(gi1 + r1 * an1);
                float h0 = n0 + z0 * (hB[2*p+0] - n0);
                float h1 = n1 + z1 * (hB[2*p+1] - n1);
                hB[2*p+0] = h0; hB[2*p+1] = h1;
                spB += h0 * ws0 + h1 * ws1;
            }
        }
        const float sA = s_bs + spA + __shfl_xor_sync(0xffffffffu, spA, 1);
        const float sB = s_bs + spB + __shfl_xor_sync(0xffffffffu, spB, 1);

        if (hid) {
            float4* hpA = reinterpret_cast<float4*>(
                hid + rowA * (TT * HH) + t * HH + jbase);
            hpA[0] = make_float4(hA[0], hA[1], hA[2], hA[3]);
            hpA[1] = make_float4(hA[4], hA[5], hA[6], hA[7]);
            float4* hpB = reinterpret_cast<float4*>(
                hid + (rowA + 1) * (TT * HH) + t * HH + jbase);
            hpB[0] = make_float4(hB[0], hB[1], hB[2], hB[3]);
            hpB[1] = make_float4(hB[4], hB[5], hB[6], hB[7]);
        }
        if (half == 0) {
            if (sumo) {
                sumo[rowA * TT + t] = sA;
                sumo[(rowA + 1) * TT + t] = sB;
            }
        } else {
            if (olog) {
                olog[rowA * (TT + 1) + t] = sA;
                olog[(rowA + 1) * (TT + 1) + t] = sB;
            }
        }
    }

    float cpA = 0.0f, cpB = 0.0f;
    #pragma unroll
    for (int i = 0; i < 8; i++) {
        const float wc = s_wcar[jbase + i];
        cpA += hA[i] * wc;
        cpB += hB[i] * wc;
    }
    const float cA = s_bc + cpA + __shfl_xor_sync(0xffffffffu, cpA, 1);
    const float cB = s_bc + cpB + __shfl_xor_sync(0xffffffffu, cpB, 1);
    if (half == 0) {
        if (carryo) { carryo[rowA] = cA; carryo[rowA + 1] = cB; }
    } else {
        if (olog) {
            olog[rowA * (TT + 1) + TT] = cA;
            olog[(rowA + 1) * (TT + 1) + TT] = cB;
        }
    }
}

extern "C" void kernel_launch(void* const* d_in, const int* in_sizes, int n_in,
                              void* d_out, int out_size) {
    const float* x       = (const float*)d_in[0];
    const float* w_ih    = (const float*)d_in[1];
    const float* w_hh    = (const float*)d_in[2];
    const float* b_ih    = (const float*)d_in[3];
    const float* b_hh    = (const float*)d_in[4];
    const float* w_sum   = (const float*)d_in[5];
    const float* b_sum   = (const float*)d_in[6];
    const float* w_carry = (const float*)d_in[7];
    const float* b_carry = (const float*)d_in[8];

    long long B = (long long)in_sizes[0] / (TT * II);
    float* out = (float*)d_out;
    long long os = (long long)out_size;

    // Output layout: concatenation of flattened (hidden_table, sum_logits,
    // carry_logit, output_logits) = 74 floats per row; fall back otherwise.
    float *hid = nullptr, *sum = nullptr, *car = nullptr, *olog = nullptr;
    if (os >= B * 74) {
        hid = out; sum = out + B * 64; car = out + B * 68; olog = out + B * 69;
    } else if (os >= B * 64) {
        hid = out;
    } else if (os >= B * 5) {
        olog = out;
    } else if (os >= B * 4) {
        sum = out;
    } else {
        car = out;
    }

    const int threads = 256;
    long long total = B;   // 2 lanes per row-pair: B/2 pairs * 2 = B threads
    int grid = (int)((total + threads - 1) / threads);
    gru_adder_kernel<<<grid, threads>>>(x, w_ih, w_hh, b_ih, b_hh,
                                        w_sum, b_sum, w_carry, b_carry,
                                        hid, sum, car, olog, (int)B);
}